// round 10
// baseline (speedup 1.0000x reference)
#include <cuda_runtime.h>
#include <cuda_bf16.h>
#include <cuda_fp16.h>
#include <cstdint>

// Problem constants (GCN_60301340836134)
constexpr int N_NODES = 100000;
constexpr int N_EDGES = 1600000;
constexpr int D_IN    = 128;
constexpr int D_OUT   = 5;
constexpr int NOUT2   = 2 * D_OUT;          // 10 fused outputs (W_l | W_r)
constexpr int AGG_PAD = 8;                  // f32 rows: [y0..y4, deg, pad, pad]
constexpr int YL_PADH = 8;                  // fp16 rows: 16B = one LDG.128

constexpr int K4      = D_IN / 4;           // 32 float4 per x row
constexpr int WPAD    = 11;                 // sW row stride (float4) -> bank-conflict-free

// Scratch (no allocations allowed; device globals)
__device__ __align__(16) __half g_ylh [N_NODES * YL_PADH];  // x@W_l^T (fp16)
__device__ __align__(16) float  g_agg [N_NODES * AGG_PAD];  // sums + deg
__device__ __align__(16) float  g_base[N_NODES * AGG_PAD];  // x@W_r^T + b_l

// ---------------------------------------------------------------------------
// Vector reductions (sm_90+)
// ---------------------------------------------------------------------------
__device__ __forceinline__ void red_add_v4(float* addr, float4 v) {
    asm volatile("red.global.add.v4.f32 [%0], {%1, %2, %3, %4};"
                 :: "l"(addr), "f"(v.x), "f"(v.y), "f"(v.z), "f"(v.w)
                 : "memory");
}
__device__ __forceinline__ void red_add_v2(float* addr, float a, float b) {
    asm volatile("red.global.add.v2.f32 [%0], {%1, %2};"
                 :: "l"(addr), "f"(a), "f"(b)
                 : "memory");
}

// ---------------------------------------------------------------------------
// Kernel 1: projection. 8 threads per node, direct coalesced LDG (no x
// staging, no in-loop barriers -> full MLP). 256 threads = 32 nodes/block.
// Grid = 3125 blocks exactly (3125 * 32 = 100000): no bounds checks needed.
//   g_ylh[node]  = fp16(x[node] @ W_l^T)
//   g_base[node] = x[node] @ W_r^T + b_l
// Also zeroes g_agg (64 float4 per block).
// ---------------------------------------------------------------------------
__global__ __launch_bounds__(256) void proj_kernel(
    const float* __restrict__ x,
    const float* __restrict__ Wl,
    const float* __restrict__ bl,
    const float* __restrict__ Wr)
{
    __shared__ float4 sW[K4 * WPAD];   // [k4][o], stride 11 -> conflict-free
    __shared__ float  sb[D_OUT];

    const int tid = threadIdx.x;
    const int g   = tid >> 3;          // node-in-block (0..31)
    const int c   = tid & 7;           // float4-chunk-in-tile (0..7)
    const int node = blockIdx.x * 32 + g;

    // fold in zeroing of g_agg: 200000 float4 / 3125 blocks = 64 per block
    if (tid < 64) {
        int zi = blockIdx.x * 64 + tid;
        ((float4*)g_agg)[zi] = make_float4(0.f, 0.f, 0.f, 0.f);
    }

    // stage weights: sW[k4*WPAD + o] = W[o][4*k4..4*k4+3]; o<5 -> Wl else Wr
    // NOTE: 320 entries > 256 threads -> MUST be a strided loop (R7 bug).
    for (int i = tid; i < K4 * NOUT2; i += 256) {
        int k4 = i / NOUT2;
        int o  = i - k4 * NOUT2;
        sW[k4 * WPAD + o] = (o < D_OUT)
            ? ((const float4*)Wl)[o * K4 + k4]
            : ((const float4*)Wr)[(o - D_OUT) * K4 + k4];
    }
    if (tid < D_OUT) sb[tid] = bl[tid];
    __syncthreads();

    // direct coalesced loads: 4 LDG.128 per thread, issued back-to-back
    const float4* x4 = (const float4*)x;
    float4 xv[4];
#pragma unroll
    for (int t = 0; t < 4; t++)
        xv[t] = x4[(size_t)node * K4 + t * 8 + c];

    float acc[NOUT2];
#pragma unroll
    for (int o = 0; o < NOUT2; o++) acc[o] = 0.f;

#pragma unroll
    for (int t = 0; t < 4; t++) {
        int kb = (t * 8 + c) * WPAD;
#pragma unroll
        for (int o = 0; o < NOUT2; o++) {
            float4 w = sW[kb + o];
            acc[o] += xv[t].x * w.x + xv[t].y * w.y
                    + xv[t].z * w.z + xv[t].w * w.w;
        }
    }

    // reduce over the 8-lane group (offsets 4,2,1) -- 30 SHFL per warp
#pragma unroll
    for (int o = 0; o < NOUT2; o++) {
        acc[o] += __shfl_xor_sync(0xFFFFFFFFu, acc[o], 4);
        acc[o] += __shfl_xor_sync(0xFFFFFFFFu, acc[o], 2);
        acc[o] += __shfl_xor_sync(0xFFFFFFFFu, acc[o], 1);
    }

    if (c == 0) {
        // fp16-packed y_l row (one 16B store)
        __half2 h01 = __floats2half2_rn(acc[0], acc[1]);
        __half2 h23 = __floats2half2_rn(acc[2], acc[3]);
        __half2 h4z = __floats2half2_rn(acc[4], 0.f);
        uint4 u;
        u.x = *(unsigned*)&h01;
        u.y = *(unsigned*)&h23;
        u.z = *(unsigned*)&h4z;
        u.w = 0u;
        ((uint4*)(g_ylh + (size_t)node * YL_PADH))[0] = u;

        // base term (f32, padded row)
        float4* bp = (float4*)(g_base + (size_t)node * AGG_PAD);
        bp[0] = make_float4(acc[5] + sb[0], acc[6] + sb[1],
                            acc[7] + sb[2], acc[8] + sb[3]);
        bp[1] = make_float4(acc[9] + sb[4], 0.f, 0.f, 0.f);
    }
}

// ---------------------------------------------------------------------------
// Kernel 2: edge scatter. 4 edges per thread (int4 index loads).
// Per edge: ONE 16B gather (8 fp16) + v4.f32 RED + v2.f32 RED.
// ---------------------------------------------------------------------------
__global__ __launch_bounds__(256) void scatter_kernel(
    const int* __restrict__ src,
    const int* __restrict__ dst)
{
    constexpr int E4 = N_EDGES / 4;  // 400000
    int t = blockIdx.x * blockDim.x + threadIdx.x;
    if (t >= E4) return;

    int4 s4 = ((const int4*)src)[t];
    int4 d4 = ((const int4*)dst)[t];

    int ss[4] = {s4.x, s4.y, s4.z, s4.w};
    int dd[4] = {d4.x, d4.y, d4.z, d4.w};

    uint4 u[4];
#pragma unroll
    for (int k = 0; k < 4; k++) {
        unsigned s = (unsigned)ss[k];
        if (s >= (unsigned)N_NODES) s = 0;  // defensive
        u[k] = ((const uint4*)(g_ylh + (size_t)s * YL_PADH))[0];
    }

#pragma unroll
    for (int k = 0; k < 4; k++) {
        unsigned d = (unsigned)dd[k];
        if (d >= (unsigned)N_NODES) continue;

        __half2 h01 = *(__half2*)&u[k].x;
        __half2 h23 = *(__half2*)&u[k].y;
        __half2 h4z = *(__half2*)&u[k].z;
        float2 f01 = __half22float2(h01);
        float2 f23 = __half22float2(h23);
        float  f4  = __low2float(h4z);

        float* ag = g_agg + (size_t)d * AGG_PAD;
        red_add_v4(ag, make_float4(f01.x, f01.y, f23.x, f23.y));
        red_add_v2(ag + 4, f4, 1.0f);
    }
}

// ---------------------------------------------------------------------------
// Kernel 3: finalize, fully coalesced.
//   out[n][o] = base[n][o] + agg[n][o] / max(deg, 1)
// ---------------------------------------------------------------------------
__global__ __launch_bounds__(256) void finalize_kernel(float* __restrict__ out)
{
    __shared__ float s_out[256 * D_OUT];  // 1280 floats = 320 float4

    int tid  = threadIdx.x;
    int node = blockIdx.x * 256 + tid;

    if (node < N_NODES) {
        const float4* ap = (const float4*)(g_agg  + (size_t)node * AGG_PAD);
        const float4* bp = (const float4*)(g_base + (size_t)node * AGG_PAD);
        float4 a0 = ap[0], a1 = ap[1];
        float4 b0 = bp[0], b1 = bp[1];

        float inv = 1.0f / fmaxf(a1.y, 1.0f);   // deg in lane 5

        s_out[tid * D_OUT + 0] = b0.x + a0.x * inv;
        s_out[tid * D_OUT + 1] = b0.y + a0.y * inv;
        s_out[tid * D_OUT + 2] = b0.z + a0.z * inv;
        s_out[tid * D_OUT + 3] = b0.w + a0.w * inv;
        s_out[tid * D_OUT + 4] = b1.x + a1.x * inv;
    }
    __syncthreads();

    int base_f  = blockIdx.x * 256 * D_OUT;
    int total_f = N_NODES * D_OUT;
#pragma unroll
    for (int j = tid; j < 320; j += 256) {
        int f = base_f + j * 4;
        if (f + 3 < total_f) {
            ((float4*)out)[base_f / 4 + j] = ((const float4*)s_out)[j];
        } else if (f < total_f) {
            for (int q = 0; q < total_f - f; q++)
                out[f + q] = s_out[j * 4 + q];
        }
    }
}

// ---------------------------------------------------------------------------
// Launch
// Inputs (metadata order): x [N*128 f32], edge_index [2*E int32 on device],
//                          W_l [5*128 f32], b_l [5 f32], W_r [5*128 f32]
// Output: [N*5 f32]
// ---------------------------------------------------------------------------
extern "C" void kernel_launch(void* const* d_in, const int* in_sizes, int n_in,
                              void* d_out, int out_size)
{
    const float* x    = (const float*)d_in[0];
    const int*   eidx = (const int*)d_in[1];
    const float* Wl   = (const float*)d_in[2];
    const float* bl   = (const float*)d_in[3];
    const float* Wr   = (const float*)d_in[4];
    float*       out  = (float*)d_out;

    const int* src = eidx;            // edge_index[0]
    const int* dst = eidx + N_EDGES;  // edge_index[1]

    {
        int blocks = N_NODES / 32;    // 3125 exactly; also zeroes g_agg
        proj_kernel<<<blocks, 256>>>(x, Wl, bl, Wr);
    }
    {
        constexpr int E4 = N_EDGES / 4;
        scatter_kernel<<<(E4 + 255) / 256, 256>>>(src, dst);
    }
    {
        int blocks = (N_NODES + 255) / 256;
        finalize_kernel<<<blocks, 256>>>(out);
    }
}

// round 11
// speedup vs baseline: 1.1349x; 1.1349x over previous
#include <cuda_runtime.h>
#include <cuda_bf16.h>
#include <cuda_fp16.h>
#include <cstdint>

// Problem constants (GCN_60301340836134)
constexpr int N_NODES = 100000;
constexpr int N_EDGES = 1600000;
constexpr int D_IN    = 128;
constexpr int D_OUT   = 5;
constexpr int NOUT2   = 2 * D_OUT;          // 10 fused outputs (W_l | W_r)
constexpr int AGG_PAD = 8;                  // f32 rows: [y0..y4, deg, pad, pad]
constexpr int YL_PADH = 8;                  // fp16 rows: 16B = one LDG.128

constexpr int K4      = D_IN / 4;           // 32 float4 per x row
constexpr int WPAD    = 11;                 // sW row stride (float4)
constexpr int NPT     = 4;                  // nodes per thread
constexpr int NPB2    = 128;                // nodes per block (32 groups * 4)

// Scratch (no allocations allowed; device globals)
__device__ __align__(16) __half g_ylh [N_NODES * YL_PADH];  // x@W_l^T (fp16)
__device__ __align__(16) float  g_agg [N_NODES * AGG_PAD];  // sums + deg
__device__ __align__(16) float  g_base[N_NODES * AGG_PAD];  // x@W_r^T + b_l

// ---------------------------------------------------------------------------
// Vector reductions (sm_90+)
// ---------------------------------------------------------------------------
__device__ __forceinline__ void red_add_v4(float* addr, float4 v) {
    asm volatile("red.global.add.v4.f32 [%0], {%1, %2, %3, %4};"
                 :: "l"(addr), "f"(v.x), "f"(v.y), "f"(v.z), "f"(v.w)
                 : "memory");
}
__device__ __forceinline__ void red_add_v2(float* addr, float a, float b) {
    asm volatile("red.global.add.v2.f32 [%0], {%1, %2};"
                 :: "l"(addr), "f"(a), "f"(b)
                 : "memory");
}

// ---------------------------------------------------------------------------
// Kernel 1: projection. 8 lanes per node-group, 4 NODES PER THREAD.
// Weight LDS amortized over 4 nodes -> 4x less smem return traffic than R9.
// No in-loop barriers; 4 coalesced LDG.128 in flight per tile.
//   g_ylh[node]  = fp16(x[node] @ W_l^T)
//   g_base[node] = x[node] @ W_r^T + b_l
// Also zeroes g_agg (256 float4 per block).
// ---------------------------------------------------------------------------
__global__ __launch_bounds__(256) void proj_kernel(
    const float* __restrict__ x,
    const float* __restrict__ Wl,
    const float* __restrict__ bl,
    const float* __restrict__ Wr)
{
    __shared__ float4 sW[K4 * WPAD];   // [k4][o], stride 11
    __shared__ float  sb[D_OUT];

    const int tid   = threadIdx.x;
    const int g     = tid >> 3;        // group in block (0..31)
    const int c     = tid & 7;         // float4-chunk within tile (0..7)
    const int nbase = blockIdx.x * NPB2 + g * NPT;

    // zero g_agg: 200000 float4 over 782 blocks * 256 threads
    {
        constexpr int AGG_F4 = (N_NODES * AGG_PAD) / 4;  // 200000
        int zi = blockIdx.x * 256 + tid;
        if (zi < AGG_F4) ((float4*)g_agg)[zi] = make_float4(0.f, 0.f, 0.f, 0.f);
    }

    // stage weights (strided loop: 320 entries > 256 threads)
    for (int i = tid; i < K4 * NOUT2; i += 256) {
        int k4 = i / NOUT2;
        int o  = i - k4 * NOUT2;
        sW[k4 * WPAD + o] = (o < D_OUT)
            ? ((const float4*)Wl)[o * K4 + k4]
            : ((const float4*)Wr)[(o - D_OUT) * K4 + k4];
    }
    if (tid < D_OUT) sb[tid] = bl[tid];
    __syncthreads();

    const float4* x4 = (const float4*)x;

    float acc[NPT][NOUT2];
#pragma unroll
    for (int j = 0; j < NPT; j++)
#pragma unroll
        for (int o = 0; o < NOUT2; o++) acc[j][o] = 0.f;

#pragma unroll
    for (int t = 0; t < 4; t++) {
        const int k4i = t * 8 + c;

        // weights once per tile, reused for 4 nodes
        float4 w[NOUT2];
#pragma unroll
        for (int o = 0; o < NOUT2; o++) w[o] = sW[k4i * WPAD + o];

        // 4 coalesced LDG.128 (lanes c=0..7 cover a 128B line per node)
        float4 xv[NPT];
#pragma unroll
        for (int j = 0; j < NPT; j++) {
            int node = nbase + j;
            int nc   = (node < N_NODES) ? node : 0;   // clamp (tail block)
            xv[j] = x4[(size_t)nc * K4 + k4i];
        }

#pragma unroll
        for (int j = 0; j < NPT; j++)
#pragma unroll
            for (int o = 0; o < NOUT2; o++)
                acc[j][o] += xv[j].x * w[o].x + xv[j].y * w[o].y
                           + xv[j].z * w[o].z + xv[j].w * w[o].w;
    }

    // reduce each (node, o) over the 8-lane group
#pragma unroll
    for (int j = 0; j < NPT; j++)
#pragma unroll
        for (int o = 0; o < NOUT2; o++) {
            acc[j][o] += __shfl_xor_sync(0xFFFFFFFFu, acc[j][o], 4);
            acc[j][o] += __shfl_xor_sync(0xFFFFFFFFu, acc[j][o], 2);
            acc[j][o] += __shfl_xor_sync(0xFFFFFFFFu, acc[j][o], 1);
        }

    if (c == 0) {
#pragma unroll
        for (int j = 0; j < NPT; j++) {
            int node = nbase + j;
            if (node >= N_NODES) break;

            __half2 h01 = __floats2half2_rn(acc[j][0], acc[j][1]);
            __half2 h23 = __floats2half2_rn(acc[j][2], acc[j][3]);
            __half2 h4z = __floats2half2_rn(acc[j][4], 0.f);
            uint4 u;
            u.x = *(unsigned*)&h01;
            u.y = *(unsigned*)&h23;
            u.z = *(unsigned*)&h4z;
            u.w = 0u;
            ((uint4*)(g_ylh + (size_t)node * YL_PADH))[0] = u;

            float4* bp = (float4*)(g_base + (size_t)node * AGG_PAD);
            bp[0] = make_float4(acc[j][5] + sb[0], acc[j][6] + sb[1],
                                acc[j][7] + sb[2], acc[j][8] + sb[3]);
            bp[1] = make_float4(acc[j][9] + sb[4], 0.f, 0.f, 0.f);
        }
    }
}

// ---------------------------------------------------------------------------
// Kernel 2: edge scatter. 4 edges per thread (int4 index loads).
// Per edge: ONE 16B gather (8 fp16) + v4.f32 RED + v2.f32 RED.
// ---------------------------------------------------------------------------
__global__ __launch_bounds__(256) void scatter_kernel(
    const int* __restrict__ src,
    const int* __restrict__ dst)
{
    constexpr int E4 = N_EDGES / 4;  // 400000
    int t = blockIdx.x * blockDim.x + threadIdx.x;
    if (t >= E4) return;

    int4 s4 = ((const int4*)src)[t];
    int4 d4 = ((const int4*)dst)[t];

    int ss[4] = {s4.x, s4.y, s4.z, s4.w};
    int dd[4] = {d4.x, d4.y, d4.z, d4.w};

    uint4 u[4];
#pragma unroll
    for (int k = 0; k < 4; k++) {
        unsigned s = (unsigned)ss[k];
        if (s >= (unsigned)N_NODES) s = 0;  // defensive
        u[k] = ((const uint4*)(g_ylh + (size_t)s * YL_PADH))[0];
    }

#pragma unroll
    for (int k = 0; k < 4; k++) {
        unsigned d = (unsigned)dd[k];
        if (d >= (unsigned)N_NODES) continue;

        __half2 h01 = *(__half2*)&u[k].x;
        __half2 h23 = *(__half2*)&u[k].y;
        __half2 h4z = *(__half2*)&u[k].z;
        float2 f01 = __half22float2(h01);
        float2 f23 = __half22float2(h23);
        float  f4  = __low2float(h4z);

        float* ag = g_agg + (size_t)d * AGG_PAD;
        red_add_v4(ag, make_float4(f01.x, f01.y, f23.x, f23.y));
        red_add_v2(ag + 4, f4, 1.0f);
    }
}

// ---------------------------------------------------------------------------
// Kernel 3: finalize, fully coalesced.
//   out[n][o] = base[n][o] + agg[n][o] / max(deg, 1)
// ---------------------------------------------------------------------------
__global__ __launch_bounds__(256) void finalize_kernel(float* __restrict__ out)
{
    __shared__ float s_out[256 * D_OUT];  // 1280 floats = 320 float4

    int tid  = threadIdx.x;
    int node = blockIdx.x * 256 + tid;

    if (node < N_NODES) {
        const float4* ap = (const float4*)(g_agg  + (size_t)node * AGG_PAD);
        const float4* bp = (const float4*)(g_base + (size_t)node * AGG_PAD);
        float4 a0 = ap[0], a1 = ap[1];
        float4 b0 = bp[0], b1 = bp[1];

        float inv = 1.0f / fmaxf(a1.y, 1.0f);   // deg in lane 5

        s_out[tid * D_OUT + 0] = b0.x + a0.x * inv;
        s_out[tid * D_OUT + 1] = b0.y + a0.y * inv;
        s_out[tid * D_OUT + 2] = b0.z + a0.z * inv;
        s_out[tid * D_OUT + 3] = b0.w + a0.w * inv;
        s_out[tid * D_OUT + 4] = b1.x + a1.x * inv;
    }
    __syncthreads();

    int base_f  = blockIdx.x * 256 * D_OUT;
    int total_f = N_NODES * D_OUT;
#pragma unroll
    for (int j = tid; j < 320; j += 256) {
        int f = base_f + j * 4;
        if (f + 3 < total_f) {
            ((float4*)out)[base_f / 4 + j] = ((const float4*)s_out)[j];
        } else if (f < total_f) {
            for (int q = 0; q < total_f - f; q++)
                out[f + q] = s_out[j * 4 + q];
        }
    }
}

// ---------------------------------------------------------------------------
// Launch
// Inputs (metadata order): x [N*128 f32], edge_index [2*E int32 on device],
//                          W_l [5*128 f32], b_l [5 f32], W_r [5*128 f32]
// Output: [N*5 f32]
// ---------------------------------------------------------------------------
extern "C" void kernel_launch(void* const* d_in, const int* in_sizes, int n_in,
                              void* d_out, int out_size)
{
    const float* x    = (const float*)d_in[0];
    const int*   eidx = (const int*)d_in[1];
    const float* Wl   = (const float*)d_in[2];
    const float* bl   = (const float*)d_in[3];
    const float* Wr   = (const float*)d_in[4];
    float*       out  = (float*)d_out;

    const int* src = eidx;            // edge_index[0]
    const int* dst = eidx + N_EDGES;  // edge_index[1]

    {
        int blocks = (N_NODES + NPB2 - 1) / NPB2;   // 782; also zeroes g_agg
        proj_kernel<<<blocks, 256>>>(x, Wl, bl, Wr);
    }
    {
        constexpr int E4 = N_EDGES / 4;
        scatter_kernel<<<(E4 + 255) / 256, 256>>>(src, dst);
    }
    {
        int blocks = (N_NODES + 255) / 256;
        finalize_kernel<<<blocks, 256>>>(out);
    }
}

// round 12
// speedup vs baseline: 1.1901x; 1.0486x over previous
#include <cuda_runtime.h>
#include <cuda_bf16.h>
#include <cuda_fp16.h>
#include <cstdint>

// Problem constants (GCN_60301340836134)
constexpr int N_NODES = 100000;
constexpr int N_EDGES = 1600000;
constexpr int D_IN    = 128;
constexpr int D_OUT   = 5;
constexpr int NOUT2   = 2 * D_OUT;          // 10 fused outputs (W_l | W_r)
constexpr int AGG_PAD = 8;                  // f32 rows: [y0..y4, deg, pad, pad]
constexpr int YL_PADH = 8;                  // fp16 rows: 16B = one LDG.128

constexpr int K4      = D_IN / 4;           // 32 float4 per x row
constexpr int WPAD    = 11;                 // sW row stride (float4)
constexpr int NPT     = 4;                  // nodes per thread
constexpr int NPB2    = 128;                // nodes per block (32 groups * 4)

// Scratch (no allocations allowed; device globals)
__device__ __align__(16) __half g_ylh [N_NODES * YL_PADH];  // x@W_l^T (fp16)
__device__ __align__(16) float  g_agg [N_NODES * AGG_PAD];  // sums + deg
__device__ __align__(16) float  g_base[N_NODES * AGG_PAD];  // x@W_r^T + b_l

// ---------------------------------------------------------------------------
// Vector reductions (sm_90+)
// ---------------------------------------------------------------------------
__device__ __forceinline__ void red_add_v4(float* addr, float4 v) {
    asm volatile("red.global.add.v4.f32 [%0], {%1, %2, %3, %4};"
                 :: "l"(addr), "f"(v.x), "f"(v.y), "f"(v.z), "f"(v.w)
                 : "memory");
}
__device__ __forceinline__ void red_add_v2(float* addr, float a, float b) {
    asm volatile("red.global.add.v2.f32 [%0], {%1, %2};"
                 :: "l"(addr), "f"(a), "f"(b)
                 : "memory");
}

// ---------------------------------------------------------------------------
// Kernel 1: projection. 8 lanes per node-group, 4 nodes per thread.
// ALL 16 LDG.128 issued up front (32KB in flight per SM at 2 CTA/SM),
// then compute with weights streamed from smem (amortized over 4 nodes).
// __launch_bounds__(256, 2) caps regs at 128 -> 2 CTA/SM.
//   g_ylh[node]  = fp16(x[node] @ W_l^T)
//   g_base[node] = x[node] @ W_r^T + b_l
// Also zeroes g_agg.
// ---------------------------------------------------------------------------
__global__ __launch_bounds__(256, 2) void proj_kernel(
    const float* __restrict__ x,
    const float* __restrict__ Wl,
    const float* __restrict__ bl,
    const float* __restrict__ Wr)
{
    __shared__ float4 sW[K4 * WPAD];   // [k4][o], stride 11
    __shared__ float  sb[D_OUT];

    const int tid   = threadIdx.x;
    const int g     = tid >> 3;        // group in block (0..31)
    const int c     = tid & 7;         // float4-chunk within tile (0..7)
    const int nbase = blockIdx.x * NPB2 + g * NPT;

    // zero g_agg: 200000 float4 over 782 blocks * 256 threads
    {
        constexpr int AGG_F4 = (N_NODES * AGG_PAD) / 4;  // 200000
        int zi = blockIdx.x * 256 + tid;
        if (zi < AGG_F4) ((float4*)g_agg)[zi] = make_float4(0.f, 0.f, 0.f, 0.f);
    }

    // stage weights (strided loop: 320 entries > 256 threads)
    for (int i = tid; i < K4 * NOUT2; i += 256) {
        int k4 = i / NOUT2;
        int o  = i - k4 * NOUT2;
        sW[k4 * WPAD + o] = (o < D_OUT)
            ? ((const float4*)Wl)[o * K4 + k4]
            : ((const float4*)Wr)[(o - D_OUT) * K4 + k4];
    }
    if (tid < D_OUT) sb[tid] = bl[tid];

    const float4* x4 = (const float4*)x;

    // ---- phase 1: issue ALL 16 coalesced LDG.128 back-to-back ----
    float4 xv[NPT][4];
#pragma unroll
    for (int j = 0; j < NPT; j++) {
        int node = nbase + j;
        int nc   = (node < N_NODES) ? node : 0;   // clamp (tail block)
        const float4* row = x4 + (size_t)nc * K4 + c;
#pragma unroll
        for (int t = 0; t < 4; t++)
            xv[j][t] = row[t * 8];
    }

    __syncthreads();   // weights visible (overlaps with LDGs in flight)

    // ---- phase 2: compute, weights streamed from smem per tile ----
    float acc[NPT][NOUT2];
#pragma unroll
    for (int j = 0; j < NPT; j++)
#pragma unroll
        for (int o = 0; o < NOUT2; o++) acc[j][o] = 0.f;

#pragma unroll
    for (int t = 0; t < 4; t++) {
        const int k4i = t * 8 + c;
#pragma unroll
        for (int o = 0; o < NOUT2; o++) {
            float4 w = sW[k4i * WPAD + o];
#pragma unroll
            for (int j = 0; j < NPT; j++)
                acc[j][o] += xv[j][t].x * w.x + xv[j][t].y * w.y
                           + xv[j][t].z * w.z + xv[j][t].w * w.w;
        }
    }

    // reduce each (node, o) over the 8-lane group
#pragma unroll
    for (int j = 0; j < NPT; j++)
#pragma unroll
        for (int o = 0; o < NOUT2; o++) {
            acc[j][o] += __shfl_xor_sync(0xFFFFFFFFu, acc[j][o], 4);
            acc[j][o] += __shfl_xor_sync(0xFFFFFFFFu, acc[j][o], 2);
            acc[j][o] += __shfl_xor_sync(0xFFFFFFFFu, acc[j][o], 1);
        }

    if (c == 0) {
#pragma unroll
        for (int j = 0; j < NPT; j++) {
            int node = nbase + j;
            if (node >= N_NODES) break;

            __half2 h01 = __floats2half2_rn(acc[j][0], acc[j][1]);
            __half2 h23 = __floats2half2_rn(acc[j][2], acc[j][3]);
            __half2 h4z = __floats2half2_rn(acc[j][4], 0.f);
            uint4 u;
            u.x = *(unsigned*)&h01;
            u.y = *(unsigned*)&h23;
            u.z = *(unsigned*)&h4z;
            u.w = 0u;
            ((uint4*)(g_ylh + (size_t)node * YL_PADH))[0] = u;

            float4* bp = (float4*)(g_base + (size_t)node * AGG_PAD);
            bp[0] = make_float4(acc[j][5] + sb[0], acc[j][6] + sb[1],
                                acc[j][7] + sb[2], acc[j][8] + sb[3]);
            bp[1] = make_float4(acc[j][9] + sb[4], 0.f, 0.f, 0.f);
        }
    }
}

// ---------------------------------------------------------------------------
// Kernel 2: edge scatter. 4 edges per thread (int4 index loads).
// Per edge: ONE 16B gather (8 fp16) + v4.f32 RED + v2.f32 RED.
// ---------------------------------------------------------------------------
__global__ __launch_bounds__(256) void scatter_kernel(
    const int* __restrict__ src,
    const int* __restrict__ dst)
{
    constexpr int E4 = N_EDGES / 4;  // 400000
    int t = blockIdx.x * blockDim.x + threadIdx.x;
    if (t >= E4) return;

    int4 s4 = ((const int4*)src)[t];
    int4 d4 = ((const int4*)dst)[t];

    int ss[4] = {s4.x, s4.y, s4.z, s4.w};
    int dd[4] = {d4.x, d4.y, d4.z, d4.w};

    uint4 u[4];
#pragma unroll
    for (int k = 0; k < 4; k++) {
        unsigned s = (unsigned)ss[k];
        if (s >= (unsigned)N_NODES) s = 0;  // defensive
        u[k] = ((const uint4*)(g_ylh + (size_t)s * YL_PADH))[0];
    }

#pragma unroll
    for (int k = 0; k < 4; k++) {
        unsigned d = (unsigned)dd[k];
        if (d >= (unsigned)N_NODES) continue;

        __half2 h01 = *(__half2*)&u[k].x;
        __half2 h23 = *(__half2*)&u[k].y;
        __half2 h4z = *(__half2*)&u[k].z;
        float2 f01 = __half22float2(h01);
        float2 f23 = __half22float2(h23);
        float  f4  = __low2float(h4z);

        float* ag = g_agg + (size_t)d * AGG_PAD;
        red_add_v4(ag, make_float4(f01.x, f01.y, f23.x, f23.y));
        red_add_v2(ag + 4, f4, 1.0f);
    }
}

// ---------------------------------------------------------------------------
// Kernel 3: finalize, fully coalesced.
//   out[n][o] = base[n][o] + agg[n][o] / max(deg, 1)
// ---------------------------------------------------------------------------
__global__ __launch_bounds__(256) void finalize_kernel(float* __restrict__ out)
{
    __shared__ float s_out[256 * D_OUT];  // 1280 floats = 320 float4

    int tid  = threadIdx.x;
    int node = blockIdx.x * 256 + tid;

    if (node < N_NODES) {
        const float4* ap = (const float4*)(g_agg  + (size_t)node * AGG_PAD);
        const float4* bp = (const float4*)(g_base + (size_t)node * AGG_PAD);
        float4 a0 = ap[0], a1 = ap[1];
        float4 b0 = bp[0], b1 = bp[1];

        float inv = 1.0f / fmaxf(a1.y, 1.0f);   // deg in lane 5

        s_out[tid * D_OUT + 0] = b0.x + a0.x * inv;
        s_out[tid * D_OUT + 1] = b0.y + a0.y * inv;
        s_out[tid * D_OUT + 2] = b0.z + a0.z * inv;
        s_out[tid * D_OUT + 3] = b0.w + a0.w * inv;
        s_out[tid * D_OUT + 4] = b1.x + a1.x * inv;
    }
    __syncthreads();

    int base_f  = blockIdx.x * 256 * D_OUT;
    int total_f = N_NODES * D_OUT;
#pragma unroll
    for (int j = tid; j < 320; j += 256) {
        int f = base_f + j * 4;
        if (f + 3 < total_f) {
            ((float4*)out)[base_f / 4 + j] = ((const float4*)s_out)[j];
        } else if (f < total_f) {
            for (int q = 0; q < total_f - f; q++)
                out[f + q] = s_out[j * 4 + q];
        }
    }
}

// ---------------------------------------------------------------------------
// Launch
// Inputs (metadata order): x [N*128 f32], edge_index [2*E int32 on device],
//                          W_l [5*128 f32], b_l [5 f32], W_r [5*128 f32]
// Output: [N*5 f32]
// ---------------------------------------------------------------------------
extern "C" void kernel_launch(void* const* d_in, const int* in_sizes, int n_in,
                              void* d_out, int out_size)
{
    const float* x    = (const float*)d_in[0];
    const int*   eidx = (const int*)d_in[1];
    const float* Wl   = (const float*)d_in[2];
    const float* bl   = (const float*)d_in[3];
    const float* Wr   = (const float*)d_in[4];
    float*       out  = (float*)d_out;

    const int* src = eidx;            // edge_index[0]
    const int* dst = eidx + N_EDGES;  // edge_index[1]

    {
        int blocks = (N_NODES + NPB2 - 1) / NPB2;   // 782; also zeroes g_agg
        proj_kernel<<<blocks, 256>>>(x, Wl, bl, Wr);
    }
    {
        constexpr int E4 = N_EDGES / 4;
        scatter_kernel<<<(E4 + 255) / 256, 256>>>(src, dst);
    }
    {
        int blocks = (N_NODES + 255) / 256;
        finalize_kernel<<<blocks, 256>>>(out);
    }
}